// round 5
// baseline (speedup 1.0000x reference)
#include <cuda_runtime.h>
#include <cstdint>

// ---------------------------------------------------------------------------
// FullGraphModel — analytic form (derivation from round 2, reconfirmed on HW
// in rounds 1-3 with rel_err == 0.0).
//
//   sum_nonzero((v - mean_nz)/std) == 0 identically (mean_nz is the mean of
//   exactly those entries); zeros stay 0. => pooled == 0 exactly =>
//   out[b] = relu(fc_b) for every graph, independent of x / edge_weight /
//   src / dst / dm_indices / fc_w and all three message-passing rounds.
//
// Measured floor analysis (R2/R3): DRAM 0%, issue <2%, dur pinned at
// ~4.6 us regardless of block shape => fixed launch/replay cost dominates.
// Single warp, widest store path (2x STG.128 when n==8 and out is aligned).
// ---------------------------------------------------------------------------

__global__ __launch_bounds__(32) void analytic_out_kernel(
    const float* __restrict__ fcb, float* __restrict__ out, int n)
{
    float r = fmaxf(__ldg(fcb), 0.0f);

    if ((n == 8) && ((reinterpret_cast<uintptr_t>(out) & 15u) == 0)) {
        // n==8, 16B-aligned: two lanes each emit one 128-bit store.
        if (threadIdx.x < 2) {
            float4 v = make_float4(r, r, r, r);
            reinterpret_cast<float4*>(out)[threadIdx.x] = v;
        }
    } else {
        for (int i = threadIdx.x; i < n; i += 32) out[i] = r;
    }
}

extern "C" void kernel_launch(void* const* d_in, const int* in_sizes, int n_in,
                              void* d_out, int out_size)
{
    // metadata order: x, edge_weight, src, dst, dm_indices, fc_w, fc_b, ...
    const float* fcb = (const float*)d_in[6];
    float* out = (float*)d_out;

    int blocks = (out_size + 31) / 32;
    if (blocks < 1) blocks = 1;
    analytic_out_kernel<<<blocks, 32>>>(fcb, out, out_size);
}

// round 6
// speedup vs baseline: 1.6643x; 1.6643x over previous
#include <cuda_runtime.h>

// ---------------------------------------------------------------------------
// FullGraphModel — analytic form (see round-2 derivation).
//
// pooled = mean over M of where(v!=0, (v-mean_nz)/std, 0) == 0 identically,
// because mean_nz is the mean of exactly the entries being centered. Hence
// out[b] = relu(fc_b) for every graph, independent of x/edges/weights/passes.
// Verified on hardware: rel_err == 0.0 in every passing round (1,2,3,5).
//
// Floor analysis (R2-R5): ncu kernel time pinned at 3.55-3.71 us regardless
// of block shape or store width; DRAM 0%, issue <2%. End-to-end wall time
// jitters +-1.5 us around ~4.6 us from harness/replay overhead. This is the
// measured-best (R2) source, reverted per the pre-committed rule after R5's
// 7.6 us outlier (kernel time unchanged => harness jitter, not regression).
// ---------------------------------------------------------------------------

__global__ __launch_bounds__(32) void analytic_out_kernel(
    const float* __restrict__ fcb, float* __restrict__ out, int n)
{
    float r = fmaxf(__ldg(fcb), 0.0f);
    int i = threadIdx.x + blockIdx.x * 32;
    if (i < n) out[i] = r;
}

extern "C" void kernel_launch(void* const* d_in, const int* in_sizes, int n_in,
                              void* d_out, int out_size)
{
    // metadata order: x, edge_weight, src, dst, dm_indices, fc_w, fc_b, ...
    const float* fcb = (const float*)d_in[6];
    float* out = (float*)d_out;

    int blocks = (out_size + 31) / 32;
    if (blocks < 1) blocks = 1;
    analytic_out_kernel<<<blocks, 32>>>(fcb, out, out_size);
}